// round 9
// baseline (speedup 1.0000x reference)
#include <cuda_runtime.h>
#include <cuda_fp16.h>
#include <math.h>
#include <stdint.h>

// ----------------------------------------------------------------------------
// DeformableCrossAttention2D, split-fp16 mma.sync + ldmatrix (sm_100-safe).
// Value GEMMs: 2-product fp16. Offset conv: 3-product fp16.
// Attention: smem-resident K(fp16)+V(fp32) per head.
// ----------------------------------------------------------------------------

// ---------------- scratch (device globals; allocation-free rule) -------------
__device__ float g_q[64 * 4096 * 32];        // (n=b*H, pix, d)
__device__ float g_k[64 * 1024 * 32];
__device__ float g_v[64 * 1024 * 32];
__device__ float g_grids[64 * 4 * 4096 * 2]; // (n, p, pix, {x,y})

__device__ __align__(16) uint32_t g_i2h[8 * 128 * 66 * 68]; // fp16-pair image hi
__device__ __align__(16) uint32_t g_i2l[8 * 128 * 66 * 68]; // lo
__device__ __align__(16) uint16_t g_wch[9 * 64 * 256];      // conv W hi
__device__ __align__(16) uint16_t g_wcl[9 * 64 * 256];      // conv W lo
__device__ __align__(16) uint16_t g_pwh[4 * 256 * 256];     // proj/out W hi
__device__ __align__(16) uint16_t g_xqh[8 * 4096 * 256];    // query^T split
__device__ __align__(16) uint16_t g_xql[8 * 4096 * 256];
__device__ __align__(16) uint16_t g_xkh[8 * 1024 * 256];    // kv^T split
__device__ __align__(16) uint16_t g_xkl[8 * 1024 * 256];
__device__ __align__(16) uint16_t g_attnh[8 * 4096 * 256];
__device__ __align__(16) uint16_t g_attnl[8 * 4096 * 256];

// ---------------- helpers ----------------------------------------------------
__device__ __forceinline__ void split_f16(float v, uint16_t& h, uint16_t& l) {
    __half hb = __float2half_rn(v);
    float r = v - __half2float(hb);
    h = __half_as_ushort(hb);
    l = __half_as_ushort(__float2half_rn(r));
}

__device__ __forceinline__ void mma_f16(float* c, const uint32_t* a, const uint32_t* b) {
    asm volatile(
        "mma.sync.aligned.m16n8k16.row.col.f32.f16.f16.f32 "
        "{%0,%1,%2,%3}, {%4,%5,%6,%7}, {%8,%9}, {%0,%1,%2,%3};"
        : "+f"(c[0]), "+f"(c[1]), "+f"(c[2]), "+f"(c[3])
        : "r"(a[0]), "r"(a[1]), "r"(a[2]), "r"(a[3]), "r"(b[0]), "r"(b[1]));
}

__device__ __forceinline__ void ldm_x4(uint32_t* r, uint32_t addr) {
    asm volatile("ldmatrix.sync.aligned.m8n8.x4.shared.b16 {%0,%1,%2,%3}, [%4];"
                 : "=r"(r[0]), "=r"(r[1]), "=r"(r[2]), "=r"(r[3]) : "r"(addr));
}

__device__ __forceinline__ uint32_t smem_u32(const void* p) {
    uint32_t a;
    asm("{ .reg .u64 t; cvta.to.shared.u64 t, %1; cvt.u32.u64 %0, t; }" : "=r"(a) : "l"(p));
    return a;
}
#define CP16(dst, src) \
    asm volatile("cp.async.cg.shared.global [%0], [%1], 16;" :: "r"(dst), "l"(src) : "memory")
#define CP_COMMIT() asm volatile("cp.async.commit_group;" ::: "memory")
#define CP_WAIT0()  asm volatile("cp.async.wait_group 0;" ::: "memory")

// ---------------- merged prep kernel -----------------------------------------
// blocks [0, 17952): pad+split query image (c-pair interleaved)
// blocks [17952, 18528): conv weights split -> [tap][oc][c]
// blocks [18528, 19552): proj/out weights hi
#define NBLK_IMG 17952
#define NBLK_W   576
#define NBLK_PW  1024

__global__ __launch_bounds__(256) void prep_all_kernel(
    const float* __restrict__ q, const float* __restrict__ cw,
    const float* __restrict__ w0, const float* __restrict__ w1,
    const float* __restrict__ w2, const float* __restrict__ w3)
{
    int blk = blockIdx.x;
    if (blk < NBLK_IMG) {
        int idx = blk * 256 + threadIdx.x;
        int b    = idx / (128 * 66 * 68);
        int rem  = idx - b * (128 * 66 * 68);
        int c2   = rem / (66 * 68);
        int rem2 = rem - c2 * (66 * 68);
        int y = rem2 / 68, x = rem2 - y * 68;
        uint16_t h0 = 0, l0 = 0, h1 = 0, l1 = 0;
        if (y >= 1 && y <= 64 && x >= 1 && x <= 64) {
            size_t base = ((size_t)(b * 256 + 2 * c2) * 64 + (y - 1)) * 64 + (x - 1);
            split_f16(q[base], h0, l0);
            split_f16(q[base + 4096], h1, l1);
        }
        g_i2h[idx] = (uint32_t)h0 | ((uint32_t)h1 << 16);
        g_i2l[idx] = (uint32_t)l0 | ((uint32_t)l1 << 16);
    } else if (blk < NBLK_IMG + NBLK_W) {
        int idx = (blk - NBLK_IMG) * 256 + threadIdx.x;
        int tap = idx >> 14;
        int rem = idx & 16383;
        int oc = rem >> 8, c = rem & 255;
        uint16_t h, l;
        split_f16(cw[(size_t)oc * 2304 + c * 9 + tap], h, l);
        g_wch[idx] = h;
        g_wcl[idx] = l;
    } else {
        int idx = (blk - NBLK_IMG - NBLK_W) * 256 + threadIdx.x;
        int slot = idx >> 16;
        int within = idx & 65535;
        const float* w = (slot == 0) ? w0 : (slot == 1) ? w1 : (slot == 2) ? w2 : w3;
        g_pwh[idx] = __half_as_ushort(__float2half_rn(w[within]));
    }
}

// ---------------- transpose+split activations --------------------------------
__global__ __launch_bounds__(256) void tsplit_kernel(
    const float* __restrict__ x, uint16_t* __restrict__ oh,
    uint16_t* __restrict__ ol, int Npix)
{
    __shared__ float tile[32][33];
    int p0 = blockIdx.x * 32, c0 = blockIdx.y * 32, b = blockIdx.z;
    int tx = threadIdx.x & 31, ty = threadIdx.x >> 5;
    const float* src = x + ((size_t)b * 256 + c0) * Npix + p0;
#pragma unroll
    for (int lq = 0; lq < 4; lq++) {
        int cc = ty + lq * 8;
        tile[cc][tx] = src[(size_t)cc * Npix + tx];
    }
    __syncthreads();
#pragma unroll
    for (int lq = 0; lq < 4; lq++) {
        int pp = ty + lq * 8;
        uint16_t h, l;
        split_f16(tile[tx][pp], h, l);
        size_t o = ((size_t)b * Npix + p0 + pp) * 256 + c0 + tx;
        oh[o] = h;
        ol[o] = l;
    }
}

// ---------------- PROJ / OUT 2-product fp16 GEMM -----------------------------
// which: 0 = q-proj, 3 = stacked k+v proj (M=512), MODE_OUT ignores which.
enum { MODE_PROJ = 0, MODE_OUT = 1 };
#define PJ_SMEM 40960

template <int MODE>
__global__ __launch_bounds__(256) void mma_gemm(
    const uint16_t* __restrict__ Ahg,
    const uint16_t* __restrict__ Bhg, const uint16_t* __restrict__ Blg,
    float* __restrict__ dst, int Npix, int which)
{
    extern __shared__ __align__(16) char smem[];
    const uint32_t smb = smem_u32(smem);

    const int t = threadIdx.x;
    const int lane = t & 31, wid = t >> 5;
    const int warp_m = wid & 3;
    const int warp_n = wid >> 2;
    const int bb = blockIdx.z;
    const int n0 = blockIdx.x * 64;
    const int m0 = blockIdx.y * 128;

    float c[2][4][4];
#pragma unroll
    for (int i = 0; i < 2; i++)
#pragma unroll
        for (int j = 0; j < 4; j++)
#pragma unroll
            for (int r = 0; r < 4; r++) c[i][j][r] = 0.f;

    const int am = t >> 1, ahalf = (t & 1) * 16;
    const int bn = t >> 2, bq = t & 3;

    auto stage = [&](int kb, int buf) {
        size_t aoff = (size_t)(m0 + am) * 256 + kb * 32 + ahalf;
        uint32_t adst = smb + buf * 10240 + (am * 40 + ahalf) * 2;
        CP16(adst, Ahg + aoff);
        CP16(adst + 16, Ahg + aoff + 8);
        size_t boff = ((size_t)bb * Npix + n0 + bn) * 256 + kb * 32 + bq * 8;
        uint32_t bdst = smb + 20480 + buf * 5120 + (bn * 40 + bq * 8) * 2;
        CP16(bdst, Bhg + boff);
        CP16(bdst + 10240, Blg + boff);
    };

    stage(0, 0);
    CP_COMMIT();

    const uint32_t aAddr = ((warp_m * 32 + (lane & 15)) * 40 + ((lane >> 4) * 8)) * 2;
    const uint32_t bAddr = ((warp_n * 32 + (lane & 7) + ((lane >> 4) << 3)) * 40
                            + (((lane >> 3) & 1) * 8)) * 2;

    for (int kb = 0; kb < 8; kb++) {
        const int buf = kb & 1;
        CP_WAIT0();
        __syncthreads();
        if (kb + 1 < 8) { stage(kb + 1, buf ^ 1); CP_COMMIT(); }

        const uint32_t baseAh = smb + buf * 10240 + aAddr;
        const uint32_t baseBh = smb + 20480 + buf * 5120 + bAddr;
        const uint32_t baseBl = smb + 30720 + buf * 5120 + bAddr;
#pragma unroll
        for (int ks = 0; ks < 2; ks++) {
            uint32_t ah[2][4], bh4[4][4], bl4[4][4];
            ldm_x4(ah[0], baseAh + ks * 32);
            ldm_x4(ah[1], baseAh + ks * 32 + 1280);
            ldm_x4(bh4[0], baseBh + ks * 32);
            ldm_x4(bh4[2], baseBh + ks * 32 + 1280);
            ldm_x4(bl4[0], baseBl + ks * 32);
            ldm_x4(bl4[2], baseBl + ks * 32 + 1280);
            uint32_t bfh[4][2], bfl[4][2];
#pragma unroll
            for (int j = 0; j < 4; j++) {
                bfh[j][0] = bh4[(j >> 1) * 2][(j & 1) * 2 + 0];
                bfh[j][1] = bh4[(j >> 1) * 2][(j & 1) * 2 + 1];
                bfl[j][0] = bl4[(j >> 1) * 2][(j & 1) * 2 + 0];
                bfl[j][1] = bl4[(j >> 1) * 2][(j & 1) * 2 + 1];
            }
#pragma unroll
            for (int i = 0; i < 2; i++)
#pragma unroll
                for (int j = 0; j < 4; j++)
                    mma_f16(c[i][j], ah[i], bfh[j]);
#pragma unroll
            for (int i = 0; i < 2; i++)
#pragma unroll
                for (int j = 0; j < 4; j++)
                    mma_f16(c[i][j], ah[i], bfl[j]);
        }
        __syncthreads();
    }

#pragma unroll
    for (int i = 0; i < 2; i++) {
#pragma unroll
        for (int j = 0; j < 4; j++) {
#pragma unroll
            for (int r = 0; r < 4; r++) {
                int mm = warp_m * 32 + i * 16 + (lane >> 2) + ((r & 2) ? 8 : 0);
                int nn = warp_n * 32 + j * 8 + (lane & 3) * 2 + (r & 1);
                float v = c[i][j][r];
                if (MODE == MODE_PROJ) {
                    int m = m0 + mm;
                    int n = n0 + nn;
                    float* dstp;
                    int mch;
                    if (which == 0) { dstp = g_q; mch = m; }
                    else { dstp = (m < 256) ? g_k : g_v; mch = m & 255; }
                    int hh = mch >> 5, d = mch & 31;
                    dstp[((size_t)(bb * 8 + hh) * Npix + n) * 32 + d] = v;
                } else {
                    int m = m0 + mm;
                    int n = n0 + nn;
                    dst[((size_t)bb * 256 + m) * 4096 + n] = v;
                }
            }
        }
    }
}

// ---------------- conv kernel (3-product, window reuse) ----------------------
#define CV_SMEM 56320

__global__ __launch_bounds__(256) void conv_tc_kernel(const float* __restrict__ bias) {
    extern __shared__ __align__(16) char smem[];
    const uint32_t smb = smem_u32(smem);
    uint32_t* Ih = (uint32_t*)smem;                 // [16][280]
    uint32_t* Il = (uint32_t*)(smem + 17920);

    const int t = threadIdx.x;
    const int lane = t & 31, wid = t >> 5;
    const int warp_m = wid & 1;
    const int warp_n = wid >> 1;
    const int tile = blockIdx.x;
    const int bb = blockIdx.y;
    const int p0 = tile * 128;
    const int py0 = tile * 2;

    float c[2][4][4];
#pragma unroll
    for (int i = 0; i < 2; i++)
#pragma unroll
        for (int j = 0; j < 4; j++)
#pragma unroll
            for (int r = 0; r < 4; r++) c[i][j][r] = 0.f;

    auto stage_w = [&](int g, int wb) {
        int cblk = g / 9, tap = g - cblk * 9;
        int oc = t >> 2, q = t & 3;
        size_t src = ((size_t)(tap * 64 + oc)) * 256 + cblk * 32 + q * 8;
        uint32_t dsth = smb + 35840 + (wb * 2560 + oc * 40 + q * 8) * 2;
        CP16(dsth, g_wch + src);
        CP16(dsth + 10240, g_wcl + src);
    };

    stage_w(0, 0);
    CP_COMMIT();

    const uint32_t aAddr = ((warp_m * 32 + (lane & 15)) * 40 + ((lane >> 4) * 8)) * 2;
    const int kq = lane & 3;

    for (int cblk = 0; cblk < 8; cblk++) {
        __syncthreads();
        for (int i = t; i < 1088; i += 256) {
            int rl = i / 17, xq = i - rl * 17;
            int c2 = rl >> 2, r = rl & 3;
            size_t src = (((size_t)(bb * 128 + cblk * 16 + c2)) * 66 + (py0 + r)) * 68 + xq * 4;
            int dstw = c2 * 280 + r * 68 + xq * 4;
            *(uint4*)(Ih + dstw) = *(const uint4*)(g_i2h + src);
            *(uint4*)(Il + dstw) = *(const uint4*)(g_i2l + src);
        }
        __syncthreads();

        for (int tap = 0; tap < 9; tap++) {
            const int g = cblk * 9 + tap;
            const int wb = g & 1;
            CP_WAIT0();
            __syncthreads();
            if (g + 1 < 72) { stage_w(g + 1, wb ^ 1); CP_COMMIT(); }

            const int rowoff = tap / 3;
            const int xoff = tap - rowoff * 3;
            const uint32_t baseWh = smb + 35840 + wb * 5120 + aAddr;
            const uint32_t baseWl = smb + 46080 + wb * 5120 + aAddr;

#pragma unroll
            for (int ks = 0; ks < 2; ks++) {
                uint32_t ah[2][4], al[2][4], bh4[4][2], bl4[4][2];
                ldm_x4(ah[0], baseWh + ks * 32);
                ldm_x4(ah[1], baseWh + ks * 32 + 1280);
                ldm_x4(al[0], baseWl + ks * 32);
                ldm_x4(al[1], baseWl + ks * 32 + 1280);
                const int c2b = ks * 8 + kq;
#pragma unroll
                for (int j = 0; j < 4; j++) {
                    int n = warp_n * 32 + j * 8 + (lane >> 2);
                    int addr = c2b * 280 + ((n >> 6) + rowoff) * 68 + (n & 63) + xoff;
                    bh4[j][0] = Ih[addr];
                    bh4[j][1] = Ih[addr + 4 * 280];
                    bl4[j][0] = Il[addr];
                    bl4[j][1] = Il[addr + 4 * 280];
                }
#pragma unroll
                for (int i = 0; i < 2; i++)
#pragma unroll
                    for (int j = 0; j < 4; j++)
                        mma_f16(c[i][j], ah[i], bh4[j]);
#pragma unroll
                for (int i = 0; i < 2; i++)
#pragma unroll
                    for (int j = 0; j < 4; j++)
                        mma_f16(c[i][j], ah[i], bl4[j]);
#pragma unroll
                for (int i = 0; i < 2; i++)
#pragma unroll
                    for (int j = 0; j < 4; j++)
                        mma_f16(c[i][j], al[i], bh4[j]);
            }
        }
    }

#pragma unroll
    for (int i = 0; i < 2; i++) {
#pragma unroll
        for (int j = 0; j < 4; j++) {
#pragma unroll
            for (int r = 0; r < 4; r++) {
                int oc = warp_m * 32 + i * 16 + (lane >> 2) + ((r & 2) ? 8 : 0);
                int nn = warp_n * 32 + j * 8 + (lane & 3) * 2 + (r & 1);
                int pix = p0 + nn;
                float w = tanhf(c[i][j][r] + __ldg(&bias[oc])) * 0.25f;
                int comp = oc & 1;
                int hh = oc >> 3, p = (oc >> 1) & 3;
                int py = pix >> 6, px = pix & 63;
                float base = comp ? (py * (2.f / 63.f) - 1.f)
                                  : (px * (2.f / 63.f) - 1.f);
                g_grids[((((size_t)(bb * 8 + hh) * 4 + p) * 4096) + pix) * 2 + comp]
                    = w + base;
            }
        }
    }
}

// ---------------- smem-resident attention ------------------------------------
// One CTA per (n, pixel-quarter). K fp16 (64KB) + V fp32 (128KB) in smem.
#define AT_SMEM (65536 + 131072)

__global__ __launch_bounds__(256) void attn_kernel2()
{
    extern __shared__ __align__(16) char smem[];
    __half* ksm = (__half*)smem;               // [1024][32]
    float*  vsm = (float*)(smem + 65536);      // [1024][32]

    const int t = threadIdx.x;
    const int lane = t & 31, wid = t >> 5;
    const int n = blockIdx.y;                  // 0..63
    const int chunk = blockIdx.x;              // 0..3
    const int b = n >> 3, hh = n & 7;

    const float* kg = g_k + (size_t)n * 32768;
    const float* vg = g_v + (size_t)n * 32768;
    for (int i = t * 4; i < 32768; i += 1024) {
        float4 k4 = *(const float4*)(kg + i);
        __half2* d = (__half2*)(ksm + i);
        d[0] = __floats2half2_rn(k4.x, k4.y);
        d[1] = __floats2half2_rn(k4.z, k4.w);
        *(float4*)(vsm + i) = *(const float4*)(vg + i);
    }
    __syncthreads();

    const float2* gpb = (const float2*)g_grids + (size_t)n * 4 * 4096;
    const int pixbase = chunk * 1024 + wid * 128;

    for (int pp = 0; pp < 128; pp++) {
        const int pix = pixbase + pp;
        float qv = g_q[((size_t)n * 4096 + pix) * 32 + lane];

        float logit[4], vs[4];
#pragma unroll
        for (int p = 0; p < 4; p++) {
            float2 g = gpb[(size_t)p * 4096 + pix];
            float x = (g.x + 1.f) * 16.f - 0.5f;
            float y = (g.y + 1.f) * 16.f - 0.5f;
            float x0f = floorf(x), y0f = floorf(y);
            float wx1 = x - x0f, wy1 = y - y0f;
            int x0 = (int)x0f, y0 = (int)y0f;
            float ks = 0.f, vv = 0.f;
#pragma unroll
            for (int dy = 0; dy < 2; dy++) {
#pragma unroll
                for (int dx = 0; dx < 2; dx++) {
                    int xi = x0 + dx, yi = y0 + dy;
                    float w = (dx ? wx1 : 1.f - wx1) * (dy ? wy1 : 1.f - wy1);
                    if ((unsigned)xi < 32u && (unsigned)yi < 32u) {
                        int off = ((yi << 5) + xi) << 5;
                        ks = fmaf(w, __half2float(ksm[off + lane]), ks);
                        vv = fmaf(w, vsm[off + lane], vv);
                    }
                }
            }
            float tsum = qv * ks;
#pragma unroll
            for (int o = 16; o > 0; o >>= 1)
                tsum += __shfl_xor_sync(0xffffffffu, tsum, o);
            logit[p] = tsum * 0.17677669529663687f;
            vs[p] = vv;
        }

        float mx = fmaxf(fmaxf(logit[0], logit[1]), fmaxf(logit[2], logit[3]));
        float e0 = expf(logit[0] - mx);
        float e1 = expf(logit[1] - mx);
        float e2 = expf(logit[2] - mx);
        float e3 = expf(logit[3] - mx);
        float inv = 1.f / (e0 + e1 + e2 + e3);
        float o = (e0 * vs[0] + e1 * vs[1] + e2 * vs[2] + e3 * vs[3]) * inv;

        uint16_t h, l;
        split_f16(o, h, l);
        size_t idx = ((size_t)b * 4096 + pix) * 256 + hh * 32 + lane;
        g_attnh[idx] = h;
        g_attnl[idx] = l;
    }
}

// ----------------------------------------------------------------------------
extern "C" void kernel_launch(void* const* d_in, const int* in_sizes, int n_in,
                              void* d_out, int out_size)
{
    (void)in_sizes; (void)n_in; (void)out_size;
    const float* query = (const float*)d_in[0];
    const float* kv    = (const float*)d_in[1];
    const float* q_w   = (const float*)d_in[2];
    const float* k_w   = (const float*)d_in[3];
    const float* v_w   = (const float*)d_in[4];
    const float* off_w = (const float*)d_in[5];
    const float* off_b = (const float*)d_in[6];
    const float* out_w = (const float*)d_in[7];
    float* out = (float*)d_out;

    cudaFuncSetAttribute(mma_gemm<MODE_PROJ>,
                         cudaFuncAttributeMaxDynamicSharedMemorySize, PJ_SMEM);
    cudaFuncSetAttribute(mma_gemm<MODE_OUT>,
                         cudaFuncAttributeMaxDynamicSharedMemorySize, PJ_SMEM);
    cudaFuncSetAttribute(conv_tc_kernel,
                         cudaFuncAttributeMaxDynamicSharedMemorySize, CV_SMEM);
    cudaFuncSetAttribute(attn_kernel2,
                         cudaFuncAttributeMaxDynamicSharedMemorySize, AT_SMEM);

    uint16_t *xqh, *xql, *xkh, *xkl, *ath, *atl, *pwh;
    cudaGetSymbolAddress((void**)&xqh, g_xqh);
    cudaGetSymbolAddress((void**)&xql, g_xql);
    cudaGetSymbolAddress((void**)&xkh, g_xkh);
    cudaGetSymbolAddress((void**)&xkl, g_xkl);
    cudaGetSymbolAddress((void**)&ath, g_attnh);
    cudaGetSymbolAddress((void**)&atl, g_attnl);
    cudaGetSymbolAddress((void**)&pwh, g_pwh);

    // idx 0: all weight/image preps
    prep_all_kernel<<<NBLK_IMG + NBLK_W + NBLK_PW, 256>>>(
        query, off_w, q_w, k_w, v_w, out_w);
    // idx 1-2: activation transpose+split
    tsplit_kernel<<<dim3(4096 / 32, 8, 8), 256>>>(query, xqh, xql, 4096);
    tsplit_kernel<<<dim3(1024 / 32, 8, 8), 256>>>(kv, xkh, xkl, 1024);
    // idx 3 (ncu capture slot): offset conv -> grids
    conv_tc_kernel<<<dim3(32, 8), 256, CV_SMEM>>>(off_b);
    // idx 4: q projection
    mma_gemm<MODE_PROJ><<<dim3(64, 2, 8), 256, PJ_SMEM>>>(
        pwh + 0 * 65536, xqh, xql, nullptr, 4096, 0);
    // idx 5: stacked k+v projection (M=512)
    mma_gemm<MODE_PROJ><<<dim3(16, 4, 8), 256, PJ_SMEM>>>(
        pwh + 1 * 65536, xkh, xkl, nullptr, 1024, 3);
    // idx 6: smem-resident attention
    attn_kernel2<<<dim3(4, 64), 256, AT_SMEM>>>();
    // idx 7: output projection
    mma_gemm<MODE_OUT><<<dim3(64, 2, 8), 256, PJ_SMEM>>>(
        pwh + 3 * 65536, ath, atl, out, 4096, 0);
}

// round 10
// speedup vs baseline: 1.6995x; 1.6995x over previous
#include <cuda_runtime.h>
#include <cuda_fp16.h>
#include <math.h>
#include <stdint.h>

// ----------------------------------------------------------------------------
// DeformableCrossAttention2D, split-fp16 mma.sync + ldmatrix (sm_100-safe).
// Value GEMMs: 2-product fp16. Offset conv: 3-product fp16, split-K x2.
// ----------------------------------------------------------------------------

// ---------------- scratch (device globals; allocation-free rule) -------------
__device__ float g_q[64 * 4096 * 32];        // (n=b*H, pix, d)
__device__ float g_k[64 * 1024 * 32];
__device__ float g_v[64 * 1024 * 32];
__device__ float g_grids[64 * 4 * 4096 * 2]; // (n, p, pix, {x,y})
__device__ float g_cpart[2 * 8 * 4096 * 64]; // conv split-K partials [z][b][pix][oc]

__device__ __align__(16) uint32_t g_i2h[8 * 128 * 66 * 68]; // fp16-pair image hi
__device__ __align__(16) uint32_t g_i2l[8 * 128 * 66 * 68]; // lo
__device__ __align__(16) uint16_t g_wch[9 * 64 * 256];      // conv W hi
__device__ __align__(16) uint16_t g_wcl[9 * 64 * 256];      // conv W lo
__device__ __align__(16) uint16_t g_pwh[4 * 256 * 256];     // proj/out W hi
__device__ __align__(16) uint16_t g_xqh[8 * 4096 * 256];    // query^T split
__device__ __align__(16) uint16_t g_xql[8 * 4096 * 256];
__device__ __align__(16) uint16_t g_xkh[8 * 1024 * 256];    // kv^T split
__device__ __align__(16) uint16_t g_xkl[8 * 1024 * 256];
__device__ __align__(16) uint16_t g_attnh[8 * 4096 * 256];
__device__ __align__(16) uint16_t g_attnl[8 * 4096 * 256];

// ---------------- helpers ----------------------------------------------------
__device__ __forceinline__ void split_f16(float v, uint16_t& h, uint16_t& l) {
    __half hb = __float2half_rn(v);
    float r = v - __half2float(hb);
    h = __half_as_ushort(hb);
    l = __half_as_ushort(__float2half_rn(r));
}

__device__ __forceinline__ void mma_f16(float* c, const uint32_t* a, const uint32_t* b) {
    asm volatile(
        "mma.sync.aligned.m16n8k16.row.col.f32.f16.f16.f32 "
        "{%0,%1,%2,%3}, {%4,%5,%6,%7}, {%8,%9}, {%0,%1,%2,%3};"
        : "+f"(c[0]), "+f"(c[1]), "+f"(c[2]), "+f"(c[3])
        : "r"(a[0]), "r"(a[1]), "r"(a[2]), "r"(a[3]), "r"(b[0]), "r"(b[1]));
}

__device__ __forceinline__ void ldm_x4(uint32_t* r, uint32_t addr) {
    asm volatile("ldmatrix.sync.aligned.m8n8.x4.shared.b16 {%0,%1,%2,%3}, [%4];"
                 : "=r"(r[0]), "=r"(r[1]), "=r"(r[2]), "=r"(r[3]) : "r"(addr));
}

__device__ __forceinline__ uint32_t smem_u32(const void* p) {
    uint32_t a;
    asm("{ .reg .u64 t; cvta.to.shared.u64 t, %1; cvt.u32.u64 %0, t; }" : "=r"(a) : "l"(p));
    return a;
}
#define CP16(dst, src) \
    asm volatile("cp.async.cg.shared.global [%0], [%1], 16;" :: "r"(dst), "l"(src) : "memory")
#define CP_COMMIT() asm volatile("cp.async.commit_group;" ::: "memory")
#define CP_WAIT0()  asm volatile("cp.async.wait_group 0;" ::: "memory")

// ---------------- merged prep kernel -----------------------------------------
#define NBLK_IMG 17952
#define NBLK_W   576
#define NBLK_PW  1024

__global__ __launch_bounds__(256) void prep_all_kernel(
    const float* __restrict__ q, const float* __restrict__ cw,
    const float* __restrict__ w0, const float* __restrict__ w1,
    const float* __restrict__ w2, const float* __restrict__ w3)
{
    int blk = blockIdx.x;
    if (blk < NBLK_IMG) {
        int idx = blk * 256 + threadIdx.x;
        int b    = idx / (128 * 66 * 68);
        int rem  = idx - b * (128 * 66 * 68);
        int c2   = rem / (66 * 68);
        int rem2 = rem - c2 * (66 * 68);
        int y = rem2 / 68, x = rem2 - y * 68;
        uint16_t h0 = 0, l0 = 0, h1 = 0, l1 = 0;
        if (y >= 1 && y <= 64 && x >= 1 && x <= 64) {
            size_t base = ((size_t)(b * 256 + 2 * c2) * 64 + (y - 1)) * 64 + (x - 1);
            split_f16(q[base], h0, l0);
            split_f16(q[base + 4096], h1, l1);
        }
        g_i2h[idx] = (uint32_t)h0 | ((uint32_t)h1 << 16);
        g_i2l[idx] = (uint32_t)l0 | ((uint32_t)l1 << 16);
    } else if (blk < NBLK_IMG + NBLK_W) {
        int idx = (blk - NBLK_IMG) * 256 + threadIdx.x;
        int tap = idx >> 14;
        int rem = idx & 16383;
        int oc = rem >> 8, c = rem & 255;
        uint16_t h, l;
        split_f16(cw[(size_t)oc * 2304 + c * 9 + tap], h, l);
        g_wch[idx] = h;
        g_wcl[idx] = l;
    } else {
        int idx = (blk - NBLK_IMG - NBLK_W) * 256 + threadIdx.x;
        int slot = idx >> 16;
        int within = idx & 65535;
        const float* w = (slot == 0) ? w0 : (slot == 1) ? w1 : (slot == 2) ? w2 : w3;
        g_pwh[idx] = __half_as_ushort(__float2half_rn(w[within]));
    }
}

// ---------------- transpose+split activations --------------------------------
__global__ __launch_bounds__(256) void tsplit_kernel(
    const float* __restrict__ x, uint16_t* __restrict__ oh,
    uint16_t* __restrict__ ol, int Npix)
{
    __shared__ float tile[32][33];
    int p0 = blockIdx.x * 32, c0 = blockIdx.y * 32, b = blockIdx.z;
    int tx = threadIdx.x & 31, ty = threadIdx.x >> 5;
    const float* src = x + ((size_t)b * 256 + c0) * Npix + p0;
#pragma unroll
    for (int lq = 0; lq < 4; lq++) {
        int cc = ty + lq * 8;
        tile[cc][tx] = src[(size_t)cc * Npix + tx];
    }
    __syncthreads();
#pragma unroll
    for (int lq = 0; lq < 4; lq++) {
        int pp = ty + lq * 8;
        uint16_t h, l;
        split_f16(tile[tx][pp], h, l);
        size_t o = ((size_t)b * Npix + p0 + pp) * 256 + c0 + tx;
        oh[o] = h;
        ol[o] = l;
    }
}

// ---------------- PROJ / OUT 2-product fp16 GEMM -----------------------------
enum { MODE_PROJ = 0, MODE_OUT = 1 };
#define PJ_SMEM 40960

template <int MODE>
__global__ __launch_bounds__(256) void mma_gemm(
    const uint16_t* __restrict__ Ahg,
    const uint16_t* __restrict__ Bhg, const uint16_t* __restrict__ Blg,
    float* __restrict__ dst, int Npix, int which)
{
    extern __shared__ __align__(16) char smem[];
    const uint32_t smb = smem_u32(smem);

    const int t = threadIdx.x;
    const int lane = t & 31, wid = t >> 5;
    const int warp_m = wid & 3;
    const int warp_n = wid >> 2;
    const int bb = blockIdx.z;
    const int n0 = blockIdx.x * 64;
    const int m0 = blockIdx.y * 128;

    float c[2][4][4];
#pragma unroll
    for (int i = 0; i < 2; i++)
#pragma unroll
        for (int j = 0; j < 4; j++)
#pragma unroll
            for (int r = 0; r < 4; r++) c[i][j][r] = 0.f;

    const int am = t >> 1, ahalf = (t & 1) * 16;
    const int bn = t >> 2, bq = t & 3;

    auto stage = [&](int kb, int buf) {
        size_t aoff = (size_t)(m0 + am) * 256 + kb * 32 + ahalf;
        uint32_t adst = smb + buf * 10240 + (am * 40 + ahalf) * 2;
        CP16(adst, Ahg + aoff);
        CP16(adst + 16, Ahg + aoff + 8);
        size_t boff = ((size_t)bb * Npix + n0 + bn) * 256 + kb * 32 + bq * 8;
        uint32_t bdst = smb + 20480 + buf * 5120 + (bn * 40 + bq * 8) * 2;
        CP16(bdst, Bhg + boff);
        CP16(bdst + 10240, Blg + boff);
    };

    stage(0, 0);
    CP_COMMIT();

    const uint32_t aAddr = ((warp_m * 32 + (lane & 15)) * 40 + ((lane >> 4) * 8)) * 2;
    const uint32_t bAddr = ((warp_n * 32 + (lane & 7) + ((lane >> 4) << 3)) * 40
                            + (((lane >> 3) & 1) * 8)) * 2;

    for (int kb = 0; kb < 8; kb++) {
        const int buf = kb & 1;
        CP_WAIT0();
        __syncthreads();
        if (kb + 1 < 8) { stage(kb + 1, buf ^ 1); CP_COMMIT(); }

        const uint32_t baseAh = smb + buf * 10240 + aAddr;
        const uint32_t baseBh = smb + 20480 + buf * 5120 + bAddr;
        const uint32_t baseBl = smb + 30720 + buf * 5120 + bAddr;
#pragma unroll
        for (int ks = 0; ks < 2; ks++) {
            uint32_t ah[2][4], bh4[4][4], bl4[4][4];
            ldm_x4(ah[0], baseAh + ks * 32);
            ldm_x4(ah[1], baseAh + ks * 32 + 1280);
            ldm_x4(bh4[0], baseBh + ks * 32);
            ldm_x4(bh4[2], baseBh + ks * 32 + 1280);
            ldm_x4(bl4[0], baseBl + ks * 32);
            ldm_x4(bl4[2], baseBl + ks * 32 + 1280);
            uint32_t bfh[4][2], bfl[4][2];
#pragma unroll
            for (int j = 0; j < 4; j++) {
                bfh[j][0] = bh4[(j >> 1) * 2][(j & 1) * 2 + 0];
                bfh[j][1] = bh4[(j >> 1) * 2][(j & 1) * 2 + 1];
                bfl[j][0] = bl4[(j >> 1) * 2][(j & 1) * 2 + 0];
                bfl[j][1] = bl4[(j >> 1) * 2][(j & 1) * 2 + 1];
            }
#pragma unroll
            for (int i = 0; i < 2; i++)
#pragma unroll
                for (int j = 0; j < 4; j++)
                    mma_f16(c[i][j], ah[i], bfh[j]);
#pragma unroll
            for (int i = 0; i < 2; i++)
#pragma unroll
                for (int j = 0; j < 4; j++)
                    mma_f16(c[i][j], ah[i], bfl[j]);
        }
        __syncthreads();
    }

#pragma unroll
    for (int i = 0; i < 2; i++) {
#pragma unroll
        for (int j = 0; j < 4; j++) {
#pragma unroll
            for (int r = 0; r < 4; r++) {
                int mm = warp_m * 32 + i * 16 + (lane >> 2) + ((r & 2) ? 8 : 0);
                int nn = warp_n * 32 + j * 8 + (lane & 3) * 2 + (r & 1);
                float v = c[i][j][r];
                if (MODE == MODE_PROJ) {
                    int m = m0 + mm;
                    int n = n0 + nn;
                    float* dstp;
                    int mch;
                    if (which == 0) { dstp = g_q; mch = m; }
                    else { dstp = (m < 256) ? g_k : g_v; mch = m & 255; }
                    int hh = mch >> 5, d = mch & 31;
                    dstp[((size_t)(bb * 8 + hh) * Npix + n) * 32 + d] = v;
                } else {
                    int m = m0 + mm;
                    int n = n0 + nn;
                    dst[((size_t)bb * 256 + m) * 4096 + n] = v;
                }
            }
        }
    }
}

// ---------------- conv kernel (3-product, window reuse, split-K x2) ----------
// blockIdx: x=pixel tile (32), y=batch (8), z=K-half (2).
// Each CTA processes c-blocks [z*4, z*4+4) and writes fp32 partials to g_cpart.
#define CV_SMEM 56320

__global__ __launch_bounds__(256) void conv_tc_kernel() {
    extern __shared__ __align__(16) char smem[];
    const uint32_t smb = smem_u32(smem);
    uint32_t* Ih = (uint32_t*)smem;                 // [16][280]
    uint32_t* Il = (uint32_t*)(smem + 17920);

    const int t = threadIdx.x;
    const int lane = t & 31, wid = t >> 5;
    const int warp_m = wid & 1;
    const int warp_n = wid >> 1;
    const int tile = blockIdx.x;
    const int bb = blockIdx.y;
    const int z = blockIdx.z;
    const int p0 = tile * 128;
    const int py0 = tile * 2;

    float c[2][4][4];
#pragma unroll
    for (int i = 0; i < 2; i++)
#pragma unroll
        for (int j = 0; j < 4; j++)
#pragma unroll
            for (int r = 0; r < 4; r++) c[i][j][r] = 0.f;

    // gi = local stage index 0..35; cblk = z*4 + gi/9, tap = gi%9
    auto stage_w = [&](int gi, int wb) {
        int cl = gi / 9, tap = gi - cl * 9;
        int cblk = z * 4 + cl;
        int oc = t >> 2, q = t & 3;
        size_t src = ((size_t)(tap * 64 + oc)) * 256 + cblk * 32 + q * 8;
        uint32_t dsth = smb + 35840 + (wb * 2560 + oc * 40 + q * 8) * 2;
        CP16(dsth, g_wch + src);
        CP16(dsth + 10240, g_wcl + src);
    };

    stage_w(0, 0);
    CP_COMMIT();

    const uint32_t aAddr = ((warp_m * 32 + (lane & 15)) * 40 + ((lane >> 4) * 8)) * 2;
    const int kq = lane & 3;

    for (int cl = 0; cl < 4; cl++) {
        const int cblk = z * 4 + cl;
        __syncthreads();
        for (int i = t; i < 1088; i += 256) {
            int rl = i / 17, xq = i - rl * 17;
            int c2 = rl >> 2, r = rl & 3;
            size_t src = (((size_t)(bb * 128 + cblk * 16 + c2)) * 66 + (py0 + r)) * 68 + xq * 4;
            int dstw = c2 * 280 + r * 68 + xq * 4;
            *(uint4*)(Ih + dstw) = *(const uint4*)(g_i2h + src);
            *(uint4*)(Il + dstw) = *(const uint4*)(g_i2l + src);
        }
        __syncthreads();

        for (int tap = 0; tap < 9; tap++) {
            const int gi = cl * 9 + tap;
            const int wb = gi & 1;
            CP_WAIT0();
            __syncthreads();
            if (gi + 1 < 36) { stage_w(gi + 1, wb ^ 1); CP_COMMIT(); }

            const int rowoff = tap / 3;
            const int xoff = tap - rowoff * 3;
            const uint32_t baseWh = smb + 35840 + wb * 5120 + aAddr;
            const uint32_t baseWl = smb + 46080 + wb * 5120 + aAddr;

#pragma unroll
            for (int ks = 0; ks < 2; ks++) {
                uint32_t ah[2][4], al[2][4], bh4[4][2], bl4[4][2];
                ldm_x4(ah[0], baseWh + ks * 32);
                ldm_x4(ah[1], baseWh + ks * 32 + 1280);
                ldm_x4(al[0], baseWl + ks * 32);
                ldm_x4(al[1], baseWl + ks * 32 + 1280);
                const int c2b = ks * 8 + kq;
#pragma unroll
                for (int j = 0; j < 4; j++) {
                    int n = warp_n * 32 + j * 8 + (lane >> 2);
                    int addr = c2b * 280 + ((n >> 6) + rowoff) * 68 + (n & 63) + xoff;
                    bh4[j][0] = Ih[addr];
                    bh4[j][1] = Ih[addr + 4 * 280];
                    bl4[j][0] = Il[addr];
                    bl4[j][1] = Il[addr + 4 * 280];
                }
#pragma unroll
                for (int i = 0; i < 2; i++)
#pragma unroll
                    for (int j = 0; j < 4; j++)
                        mma_f16(c[i][j], ah[i], bh4[j]);
#pragma unroll
                for (int i = 0; i < 2; i++)
#pragma unroll
                    for (int j = 0; j < 4; j++)
                        mma_f16(c[i][j], ah[i], bl4[j]);
#pragma unroll
                for (int i = 0; i < 2; i++)
#pragma unroll
                    for (int j = 0; j < 4; j++)
                        mma_f16(c[i][j], al[i], bh4[j]);
            }
        }
    }

    // partial epilogue -> g_cpart[z][b][pix][oc] (32B-contiguous per 8-oc run)
#pragma unroll
    for (int i = 0; i < 2; i++) {
#pragma unroll
        for (int j = 0; j < 4; j++) {
#pragma unroll
            for (int r = 0; r < 4; r++) {
                int oc = warp_m * 32 + i * 16 + (lane >> 2) + ((r & 2) ? 8 : 0);
                int nn = warp_n * 32 + j * 8 + (lane & 3) * 2 + (r & 1);
                g_cpart[((size_t)(z * 8 + bb) * 4096 + p0 + nn) * 64 + oc] = c[i][j][r];
            }
        }
    }
}

// ---------------- conv combine: sum halves + bias + tanh + base grid ---------
// grid (32 tiles, 8 b), 256 threads. Tile = 128 pixels x 64 oc.
__global__ __launch_bounds__(256) void conv_combine_kernel(const float* __restrict__ bias)
{
    __shared__ float s[128][65];
    const int t = threadIdx.x;
    const int tile = blockIdx.x, b = blockIdx.y;
    const int p0 = tile * 128;

    const float* src0 = g_cpart + ((size_t)b * 4096 + p0) * 64;
    const float* src1 = g_cpart + ((size_t)(8 + b) * 4096 + p0) * 64;
#pragma unroll
    for (int k = 0; k < 8; k++) {
        int vec = t + k * 256;              // 0..2047 float4s
        int pixL = vec >> 4, oc4 = (vec & 15) * 4;
        float4 a = *(const float4*)(src0 + pixL * 64 + oc4);
        float4 bb4 = *(const float4*)(src1 + pixL * 64 + oc4);
        s[pixL][oc4 + 0] = a.x + bb4.x;
        s[pixL][oc4 + 1] = a.y + bb4.y;
        s[pixL][oc4 + 2] = a.z + bb4.z;
        s[pixL][oc4 + 3] = a.w + bb4.w;
    }
    __syncthreads();

    const int pixL = t & 127;
    const int mg = t >> 7;                  // 0 or 1
    const int pix = p0 + pixL;
    const int px = pix & 63, py = pix >> 6;
    const float bx = px * (2.f / 63.f) - 1.f;
    const float by = py * (2.f / 63.f) - 1.f;
    float2* gout = (float2*)g_grids;
#pragma unroll
    for (int mi = 0; mi < 16; mi++) {
        int m = mg * 16 + mi;               // plane 0..31
        int oc = 2 * m;
        float w0 = tanhf(s[pixL][oc] + __ldg(&bias[oc])) * 0.25f + bx;
        float w1 = tanhf(s[pixL][oc + 1] + __ldg(&bias[oc + 1])) * 0.25f + by;
        int hh = m >> 2, p = m & 3;
        gout[((size_t)((b * 8 + hh) * 4 + p) * 4096) + pix] = make_float2(w0, w1);
    }
}

// ---------------- attention (round-7 version: global loads, high occupancy) --
__global__ __launch_bounds__(256) void attn_kernel()
{
    int gw   = blockIdx.x * 8 + (threadIdx.x >> 5);
    int lane = threadIdx.x & 31;
    int n    = gw >> 12;
    int pix  = gw & 4095;
    int b    = n >> 3;
    int hh   = n & 7;

    float qv = g_q[((size_t)n * 4096 + pix) * 32 + lane];
    const float* kb = g_k + (size_t)n * 1024 * 32;
    const float* vb = g_v + (size_t)n * 1024 * 32;
    const float2* gp = (const float2*)g_grids + (size_t)n * 4 * 4096 + pix;

    float logit[4], vs[4];
#pragma unroll
    for (int p = 0; p < 4; p++) {
        float2 g = gp[(size_t)p * 4096];
        float x = (g.x + 1.f) * 16.f - 0.5f;
        float y = (g.y + 1.f) * 16.f - 0.5f;
        float x0f = floorf(x), y0f = floorf(y);
        float wx1 = x - x0f, wy1 = y - y0f;
        int x0 = (int)x0f, y0 = (int)y0f;
        float ks = 0.f, vv = 0.f;
#pragma unroll
        for (int dy = 0; dy < 2; dy++) {
#pragma unroll
            for (int dx = 0; dx < 2; dx++) {
                int xi = x0 + dx, yi = y0 + dy;
                float w = (dx ? wx1 : 1.f - wx1) * (dy ? wy1 : 1.f - wy1);
                if ((unsigned)xi < 32u && (unsigned)yi < 32u) {
                    int off = ((yi << 5) + xi) << 5;
                    ks = fmaf(w, kb[off + lane], ks);
                    vv = fmaf(w, vb[off + lane], vv);
                }
            }
        }
        float tsum = qv * ks;
#pragma unroll
        for (int o = 16; o > 0; o >>= 1)
            tsum += __shfl_xor_sync(0xffffffffu, tsum, o);
        logit[p] = tsum * 0.17677669529663687f;
        vs[p] = vv;
    }

    float mx = fmaxf(fmaxf(logit[0], logit[1]), fmaxf(logit[2], logit[3]));
    float e0 = expf(logit[0] - mx);
    float e1 = expf(logit[1] - mx);
    float e2 = expf(logit[2] - mx);
    float e3 = expf(logit[3] - mx);
    float inv = 1.f / (e0 + e1 + e2 + e3);
    float o = (e0 * vs[0] + e1 * vs[1] + e2 * vs[2] + e3 * vs[3]) * inv;

    uint16_t h, l;
    split_f16(o, h, l);
    size_t idx = ((size_t)b * 4096 + pix) * 256 + hh * 32 + lane;
    g_attnh[idx] = h;
    g_attnl[idx] = l;
}

// ----------------------------------------------------------------------------
extern "C" void kernel_launch(void* const* d_in, const int* in_sizes, int n_in,
                              void* d_out, int out_size)
{
    (void)in_sizes; (void)n_in; (void)out_size;
    const float* query = (const float*)d_in[0];
    const float* kv    = (const float*)d_in[1];
    const float* q_w   = (const float*)d_in[2];
    const float* k_w   = (const float*)d_in[3];
    const float* v_w   = (const float*)d_in[4];
    const float* off_w = (const float*)d_in[5];
    const float* off_b = (const float*)d_in[6];
    const float* out_w = (const float*)d_in[7];
    float* out = (float*)d_out;

    cudaFuncSetAttribute(mma_gemm<MODE_PROJ>,
                         cudaFuncAttributeMaxDynamicSharedMemorySize, PJ_SMEM);
    cudaFuncSetAttribute(mma_gemm<MODE_OUT>,
                         cudaFuncAttributeMaxDynamicSharedMemorySize, PJ_SMEM);
    cudaFuncSetAttribute(conv_tc_kernel,
                         cudaFuncAttributeMaxDynamicSharedMemorySize, CV_SMEM);

    uint16_t *xqh, *xql, *xkh, *xkl, *ath, *atl, *pwh;
    cudaGetSymbolAddress((void**)&xqh, g_xqh);
    cudaGetSymbolAddress((void**)&xql, g_xql);
    cudaGetSymbolAddress((void**)&xkh, g_xkh);
    cudaGetSymbolAddress((void**)&xkl, g_xkl);
    cudaGetSymbolAddress((void**)&ath, g_attnh);
    cudaGetSymbolAddress((void**)&atl, g_attnl);
    cudaGetSymbolAddress((void**)&pwh, g_pwh);

    // idx 0: merged preps
    prep_all_kernel<<<NBLK_IMG + NBLK_W + NBLK_PW, 256>>>(
        query, off_w, q_w, k_w, v_w, out_w);
    // idx 1-2: activation transpose+split
    tsplit_kernel<<<dim3(4096 / 32, 8, 8), 256>>>(query, xqh, xql, 4096);
    tsplit_kernel<<<dim3(1024 / 32, 8, 8), 256>>>(kv, xkh, xkl, 1024);
    // idx 3 (ncu capture slot): offset conv split-K x2
    conv_tc_kernel<<<dim3(32, 8, 2), 256, CV_SMEM>>>();
    // idx 4: combine halves + tanh + base grid
    conv_combine_kernel<<<dim3(32, 8), 256>>>(off_b);
    // idx 5: q projection
    mma_gemm<MODE_PROJ><<<dim3(64, 2, 8), 256, PJ_SMEM>>>(
        pwh + 0 * 65536, xqh, xql, nullptr, 4096, 0);
    // idx 6: stacked k+v projection (M=512)
    mma_gemm<MODE_PROJ><<<dim3(16, 4, 8), 256, PJ_SMEM>>>(
        pwh + 1 * 65536, xkh, xkl, nullptr, 1024, 3);
    // idx 7: attention
    attn_kernel<<<(64 * 4096) / 8, 256>>>();
    // idx 8: output projection
    mma_gemm<MODE_OUT><<<dim3(64, 2, 8), 256, PJ_SMEM>>>(
        pwh + 3 * 65536, ath, atl, out, 4096, 0);
}

// round 12
// speedup vs baseline: 1.7276x; 1.0165x over previous
#include <cuda_runtime.h>
#include <cuda_fp16.h>
#include <math.h>
#include <stdint.h>

// ----------------------------------------------------------------------------
// DeformableCrossAttention2D, split-fp16 mma.sync + ldmatrix (sm_100-safe).
// Value GEMMs: 2-product fp16. Offset conv: 3-product fp16, split-K x2,
// forced 3 CTAs/SM.
// ----------------------------------------------------------------------------

// ---------------- scratch (device globals; allocation-free rule) -------------
__device__ float g_q[64 * 4096 * 32];        // (n=b*H, pix, d)
__device__ float g_k[64 * 1024 * 32];
__device__ float g_v[64 * 1024 * 32];
__device__ float g_grids[64 * 4 * 4096 * 2]; // (n, p, pix, {x,y})
__device__ float g_cpart[2 * 8 * 4096 * 64]; // conv split-K partials [z][b][pix][oc]

__device__ __align__(16) uint32_t g_i2h[8 * 128 * 66 * 68]; // fp16-pair image hi
__device__ __align__(16) uint32_t g_i2l[8 * 128 * 66 * 68]; // lo
__device__ __align__(16) uint16_t g_wch[9 * 64 * 256];      // conv W hi
__device__ __align__(16) uint16_t g_wcl[9 * 64 * 256];      // conv W lo
__device__ __align__(16) uint16_t g_pwh[4 * 256 * 256];     // proj/out W hi
__device__ __align__(16) uint16_t g_xqh[8 * 4096 * 256];    // query^T split
__device__ __align__(16) uint16_t g_xql[8 * 4096 * 256];
__device__ __align__(16) uint16_t g_xkh[8 * 1024 * 256];    // kv^T split
__device__ __align__(16) uint16_t g_xkl[8 * 1024 * 256];
__device__ __align__(16) uint16_t g_attnh[8 * 4096 * 256];
__device__ __align__(16) uint16_t g_attnl[8 * 4096 * 256];

// ---------------- helpers ----------------------------------------------------
__device__ __forceinline__ void split_f16(float v, uint16_t& h, uint16_t& l) {
    __half hb = __float2half_rn(v);
    float r = v - __half2float(hb);
    h = __half_as_ushort(hb);
    l = __half_as_ushort(__float2half_rn(r));
}

__device__ __forceinline__ void mma_f16(float* c, const uint32_t* a, const uint32_t* b) {
    asm volatile(
        "mma.sync.aligned.m16n8k16.row.col.f32.f16.f16.f32 "
        "{%0,%1,%2,%3}, {%4,%5,%6,%7}, {%8,%9}, {%0,%1,%2,%3};"
        : "+f"(c[0]), "+f"(c[1]), "+f"(c[2]), "+f"(c[3])
        : "r"(a[0]), "r"(a[1]), "r"(a[2]), "r"(a[3]), "r"(b[0]), "r"(b[1]));
}

__device__ __forceinline__ void ldm_x4(uint32_t* r, uint32_t addr) {
    asm volatile("ldmatrix.sync.aligned.m8n8.x4.shared.b16 {%0,%1,%2,%3}, [%4];"
                 : "=r"(r[0]), "=r"(r[1]), "=r"(r[2]), "=r"(r[3]) : "r"(addr));
}

__device__ __forceinline__ uint32_t smem_u32(const void* p) {
    uint32_t a;
    asm("{ .reg .u64 t; cvta.to.shared.u64 t, %1; cvt.u32.u64 %0, t; }" : "=r"(a) : "l"(p));
    return a;
}
#define CP16(dst, src) \
    asm volatile("cp.async.cg.shared.global [%0], [%1], 16;" :: "r"(dst), "l"(src) : "memory")
#define CP_COMMIT() asm volatile("cp.async.commit_group;" ::: "memory")
#define CP_WAIT0()  asm volatile("cp.async.wait_group 0;" ::: "memory")

// ---------------- merged prep kernel -----------------------------------------
#define NBLK_IMG 17952
#define NBLK_W   576
#define NBLK_PW  1024

__global__ __launch_bounds__(256) void prep_all_kernel(
    const float* __restrict__ q, const float* __restrict__ cw,
    const float* __restrict__ w0, const float* __restrict__ w1,
    const float* __restrict__ w2, const float* __restrict__ w3)
{
    int blk = blockIdx.x;
    if (blk < NBLK_IMG) {
        int idx = blk * 256 + threadIdx.x;
        int b    = idx / (128 * 66 * 68);
        int rem  = idx - b * (128 * 66 * 68);
        int c2   = rem / (66 * 68);
        int rem2 = rem - c2 * (66 * 68);
        int y = rem2 / 68, x = rem2 - y * 68;
        uint16_t h0 = 0, l0 = 0, h1 = 0, l1 = 0;
        if (y >= 1 && y <= 64 && x >= 1 && x <= 64) {
            size_t base = ((size_t)(b * 256 + 2 * c2) * 64 + (y - 1)) * 64 + (x - 1);
            split_f16(q[base], h0, l0);
            split_f16(q[base + 4096], h1, l1);
        }
        g_i2h[idx] = (uint32_t)h0 | ((uint32_t)h1 << 16);
        g_i2l[idx] = (uint32_t)l0 | ((uint32_t)l1 << 16);
    } else if (blk < NBLK_IMG + NBLK_W) {
        int idx = (blk - NBLK_IMG) * 256 + threadIdx.x;
        int tap = idx >> 14;
        int rem = idx & 16383;
        int oc = rem >> 8, c = rem & 255;
        uint16_t h, l;
        split_f16(cw[(size_t)oc * 2304 + c * 9 + tap], h, l);
        g_wch[idx] = h;
        g_wcl[idx] = l;
    } else {
        int idx = (blk - NBLK_IMG - NBLK_W) * 256 + threadIdx.x;
        int slot = idx >> 16;
        int within = idx & 65535;
        const float* w = (slot == 0) ? w0 : (slot == 1) ? w1 : (slot == 2) ? w2 : w3;
        g_pwh[idx] = __half_as_ushort(__float2half_rn(w[within]));
    }
}

// ---------------- transpose+split activations --------------------------------
__global__ __launch_bounds__(256) void tsplit_kernel(
    const float* __restrict__ x, uint16_t* __restrict__ oh,
    uint16_t* __restrict__ ol, int Npix)
{
    __shared__ float tile[32][33];
    int p0 = blockIdx.x * 32, c0 = blockIdx.y * 32, b = blockIdx.z;
    int tx = threadIdx.x & 31, ty = threadIdx.x >> 5;
    const float* src = x + ((size_t)b * 256 + c0) * Npix + p0;
#pragma unroll
    for (int lq = 0; lq < 4; lq++) {
        int cc = ty + lq * 8;
        tile[cc][tx] = src[(size_t)cc * Npix + tx];
    }
    __syncthreads();
#pragma unroll
    for (int lq = 0; lq < 4; lq++) {
        int pp = ty + lq * 8;
        uint16_t h, l;
        split_f16(tile[tx][pp], h, l);
        size_t o = ((size_t)b * Npix + p0 + pp) * 256 + c0 + tx;
        oh[o] = h;
        ol[o] = l;
    }
}

// ---------------- PROJ / OUT 2-product fp16 GEMM -----------------------------
enum { MODE_PROJ = 0, MODE_OUT = 1 };
#define PJ_SMEM 40960

template <int MODE>
__global__ __launch_bounds__(256) void mma_gemm(
    const uint16_t* __restrict__ Ahg,
    const uint16_t* __restrict__ Bhg, const uint16_t* __restrict__ Blg,
    float* __restrict__ dst, int Npix, int which)
{
    extern __shared__ __align__(16) char smem[];
    const uint32_t smb = smem_u32(smem);

    const int t = threadIdx.x;
    const int lane = t & 31, wid = t >> 5;
    const int warp_m = wid & 3;
    const int warp_n = wid >> 2;
    const int bb = blockIdx.z;
    const int n0 = blockIdx.x * 64;
    const int m0 = blockIdx.y * 128;

    float c[2][4][4];
#pragma unroll
    for (int i = 0; i < 2; i++)
#pragma unroll
        for (int j = 0; j < 4; j++)
#pragma unroll
            for (int r = 0; r < 4; r++) c[i][j][r] = 0.f;

    const int am = t >> 1, ahalf = (t & 1) * 16;
    const int bn = t >> 2, bq = t & 3;

    auto stage = [&](int kb, int buf) {
        size_t aoff = (size_t)(m0 + am) * 256 + kb * 32 + ahalf;
        uint32_t adst = smb + buf * 10240 + (am * 40 + ahalf) * 2;
        CP16(adst, Ahg + aoff);
        CP16(adst + 16, Ahg + aoff + 8);
        size_t boff = ((size_t)bb * Npix + n0 + bn) * 256 + kb * 32 + bq * 8;
        uint32_t bdst = smb + 20480 + buf * 5120 + (bn * 40 + bq * 8) * 2;
        CP16(bdst, Bhg + boff);
        CP16(bdst + 10240, Blg + boff);
    };

    stage(0, 0);
    CP_COMMIT();

    const uint32_t aAddr = ((warp_m * 32 + (lane & 15)) * 40 + ((lane >> 4) * 8)) * 2;
    const uint32_t bAddr = ((warp_n * 32 + (lane & 7) + ((lane >> 4) << 3)) * 40
                            + (((lane >> 3) & 1) * 8)) * 2;

    for (int kb = 0; kb < 8; kb++) {
        const int buf = kb & 1;
        CP_WAIT0();
        __syncthreads();
        if (kb + 1 < 8) { stage(kb + 1, buf ^ 1); CP_COMMIT(); }

        const uint32_t baseAh = smb + buf * 10240 + aAddr;
        const uint32_t baseBh = smb + 20480 + buf * 5120 + bAddr;
        const uint32_t baseBl = smb + 30720 + buf * 5120 + bAddr;
#pragma unroll
        for (int ks = 0; ks < 2; ks++) {
            uint32_t ah[2][4], bh4[4][4], bl4[4][4];
            ldm_x4(ah[0], baseAh + ks * 32);
            ldm_x4(ah[1], baseAh + ks * 32 + 1280);
            ldm_x4(bh4[0], baseBh + ks * 32);
            ldm_x4(bh4[2], baseBh + ks * 32 + 1280);
            ldm_x4(bl4[0], baseBl + ks * 32);
            ldm_x4(bl4[2], baseBl + ks * 32 + 1280);
            uint32_t bfh[4][2], bfl[4][2];
#pragma unroll
            for (int j = 0; j < 4; j++) {
                bfh[j][0] = bh4[(j >> 1) * 2][(j & 1) * 2 + 0];
                bfh[j][1] = bh4[(j >> 1) * 2][(j & 1) * 2 + 1];
                bfl[j][0] = bl4[(j >> 1) * 2][(j & 1) * 2 + 0];
                bfl[j][1] = bl4[(j >> 1) * 2][(j & 1) * 2 + 1];
            }
#pragma unroll
            for (int i = 0; i < 2; i++)
#pragma unroll
                for (int j = 0; j < 4; j++)
                    mma_f16(c[i][j], ah[i], bfh[j]);
#pragma unroll
            for (int i = 0; i < 2; i++)
#pragma unroll
                for (int j = 0; j < 4; j++)
                    mma_f16(c[i][j], ah[i], bfl[j]);
        }
        __syncthreads();
    }

#pragma unroll
    for (int i = 0; i < 2; i++) {
#pragma unroll
        for (int j = 0; j < 4; j++) {
#pragma unroll
            for (int r = 0; r < 4; r++) {
                int mm = warp_m * 32 + i * 16 + (lane >> 2) + ((r & 2) ? 8 : 0);
                int nn = warp_n * 32 + j * 8 + (lane & 3) * 2 + (r & 1);
                float v = c[i][j][r];
                if (MODE == MODE_PROJ) {
                    int m = m0 + mm;
                    int n = n0 + nn;
                    float* dstp;
                    int mch;
                    if (which == 0) { dstp = g_q; mch = m; }
                    else { dstp = (m < 256) ? g_k : g_v; mch = m & 255; }
                    int hh = mch >> 5, d = mch & 31;
                    dstp[((size_t)(bb * 8 + hh) * Npix + n) * 32 + d] = v;
                } else {
                    int m = m0 + mm;
                    int n = n0 + nn;
                    dst[((size_t)bb * 256 + m) * 4096 + n] = v;
                }
            }
        }
    }
}

// ---------------- conv kernel (3-product, window reuse, split-K x2) ----------
// blockIdx: x=pixel tile (32), y=batch (8), z=K-half (2).
// __launch_bounds__(256, 3): cap regs at 85 -> 3 CTAs/SM (was 86 -> 2 CTAs).
#define CV_SMEM 56320

__global__ __launch_bounds__(256, 3) void conv_tc_kernel() {
    extern __shared__ __align__(16) char smem[];
    const uint32_t smb = smem_u32(smem);
    uint32_t* Ih = (uint32_t*)smem;                 // [16][280]
    uint32_t* Il = (uint32_t*)(smem + 17920);

    const int t = threadIdx.x;
    const int lane = t & 31, wid = t >> 5;
    const int warp_m = wid & 1;
    const int warp_n = wid >> 1;
    const int tile = blockIdx.x;
    const int bb = blockIdx.y;
    const int z = blockIdx.z;
    const int p0 = tile * 128;
    const int py0 = tile * 2;

    float c[2][4][4];
#pragma unroll
    for (int i = 0; i < 2; i++)
#pragma unroll
        for (int j = 0; j < 4; j++)
#pragma unroll
            for (int r = 0; r < 4; r++) c[i][j][r] = 0.f;

    auto stage_w = [&](int gi, int wb) {
        int cl = gi / 9, tap = gi - cl * 9;
        int cblk = z * 4 + cl;
        int oc = t >> 2, q = t & 3;
        size_t src = ((size_t)(tap * 64 + oc)) * 256 + cblk * 32 + q * 8;
        uint32_t dsth = smb + 35840 + (wb * 2560 + oc * 40 + q * 8) * 2;
        CP16(dsth, g_wch + src);
        CP16(dsth + 10240, g_wcl + src);
    };

    stage_w(0, 0);
    CP_COMMIT();

    const uint32_t aAddr = ((warp_m * 32 + (lane & 15)) * 40 + ((lane >> 4) * 8)) * 2;
    const int kq = lane & 3;

    for (int cl = 0; cl < 4; cl++) {
        const int cblk = z * 4 + cl;
        __syncthreads();
        for (int i = t; i < 1088; i += 256) {
            int rl = i / 17, xq = i - rl * 17;
            int c2 = rl >> 2, r = rl & 3;
            size_t src = (((size_t)(bb * 128 + cblk * 16 + c2)) * 66 + (py0 + r)) * 68 + xq * 4;
            int dstw = c2 * 280 + r * 68 + xq * 4;
            *(uint4*)(Ih + dstw) = *(const uint4*)(g_i2h + src);
            *(uint4*)(Il + dstw) = *(const uint4*)(g_i2l + src);
        }
        __syncthreads();

        for (int tap = 0; tap < 9; tap++) {
            const int gi = cl * 9 + tap;
            const int wb = gi & 1;
            CP_WAIT0();
            __syncthreads();
            if (gi + 1 < 36) { stage_w(gi + 1, wb ^ 1); CP_COMMIT(); }

            const int rowoff = tap / 3;
            const int xoff = tap - rowoff * 3;
            const uint32_t baseWh = smb + 35840 + wb * 5120 + aAddr;
            const uint32_t baseWl = smb + 46080 + wb * 5120 + aAddr;

#pragma unroll
            for (int ks = 0; ks < 2; ks++) {
                uint32_t ah[2][4], al[2][4], bh4[4][2], bl4[4][2];
                ldm_x4(ah[0], baseWh + ks * 32);
                ldm_x4(ah[1], baseWh + ks * 32 + 1280);
                ldm_x4(al[0], baseWl + ks * 32);
                ldm_x4(al[1], baseWl + ks * 32 + 1280);
                const int c2b = ks * 8 + kq;
#pragma unroll
                for (int j = 0; j < 4; j++) {
                    int n = warp_n * 32 + j * 8 + (lane >> 2);
                    int addr = c2b * 280 + ((n >> 6) + rowoff) * 68 + (n & 63) + xoff;
                    bh4[j][0] = Ih[addr];
                    bh4[j][1] = Ih[addr + 4 * 280];
                    bl4[j][0] = Il[addr];
                    bl4[j][1] = Il[addr + 4 * 280];
                }
#pragma unroll
                for (int i = 0; i < 2; i++)
#pragma unroll
                    for (int j = 0; j < 4; j++)
                        mma_f16(c[i][j], ah[i], bh4[j]);
#pragma unroll
                for (int i = 0; i < 2; i++)
#pragma unroll
                    for (int j = 0; j < 4; j++)
                        mma_f16(c[i][j], ah[i], bl4[j]);
#pragma unroll
                for (int i = 0; i < 2; i++)
#pragma unroll
                    for (int j = 0; j < 4; j++)
                        mma_f16(c[i][j], al[i], bh4[j]);
            }
        }
    }

#pragma unroll
    for (int i = 0; i < 2; i++) {
#pragma unroll
        for (int j = 0; j < 4; j++) {
#pragma unroll
            for (int r = 0; r < 4; r++) {
                int oc = warp_m * 32 + i * 16 + (lane >> 2) + ((r & 2) ? 8 : 0);
                int nn = warp_n * 32 + j * 8 + (lane & 3) * 2 + (r & 1);
                g_cpart[((size_t)(z * 8 + bb) * 4096 + p0 + nn) * 64 + oc] = c[i][j][r];
            }
        }
    }
}

// ---------------- conv combine: sum halves + bias + tanh + base grid ---------
__global__ __launch_bounds__(256) void conv_combine_kernel(const float* __restrict__ bias)
{
    __shared__ float s[128][65];
    const int t = threadIdx.x;
    const int tile = blockIdx.x, b = blockIdx.y;
    const int p0 = tile * 128;

    const float* src0 = g_cpart + ((size_t)b * 4096 + p0) * 64;
    const float* src1 = g_cpart + ((size_t)(8 + b) * 4096 + p0) * 64;
#pragma unroll
    for (int k = 0; k < 8; k++) {
        int vec = t + k * 256;
        int pixL = vec >> 4, oc4 = (vec & 15) * 4;
        float4 a = *(const float4*)(src0 + pixL * 64 + oc4);
        float4 bb4 = *(const float4*)(src1 + pixL * 64 + oc4);
        s[pixL][oc4 + 0] = a.x + bb4.x;
        s[pixL][oc4 + 1] = a.y + bb4.y;
        s[pixL][oc4 + 2] = a.z + bb4.z;
        s[pixL][oc4 + 3] = a.w + bb4.w;
    }
    __syncthreads();

    const int pixL = t & 127;
    const int mg = t >> 7;
    const int pix = p0 + pixL;
    const int px = pix & 63, py = pix >> 6;
    const float bx = px * (2.f / 63.f) - 1.f;
    const float by = py * (2.f / 63.f) - 1.f;
    float2* gout = (float2*)g_grids;
#pragma unroll
    for (int mi = 0; mi < 16; mi++) {
        int m = mg * 16 + mi;
        int oc = 2 * m;
        float w0 = tanhf(s[pixL][oc] + __ldg(&bias[oc])) * 0.25f + bx;
        float w1 = tanhf(s[pixL][oc + 1] + __ldg(&bias[oc + 1])) * 0.25f + by;
        int hh = m >> 2, p = m & 3;
        gout[((size_t)((b * 8 + hh) * 4 + p) * 4096) + pix] = make_float2(w0, w1);
    }
}

// ---------------- attention (global loads, high occupancy) -------------------
__global__ __launch_bounds__(256) void attn_kernel()
{
    int gw   = blockIdx.x * 8 + (threadIdx.x >> 5);
    int lane = threadIdx.x & 31;
    int n    = gw >> 12;
    int pix  = gw & 4095;
    int b    = n >> 3;
    int hh   = n & 7;

    float qv = g_q[((size_t)n * 4096 + pix) * 32 + lane];
    const float* kb = g_k + (size_t)n * 1024 * 32;
    const float* vb = g_v + (size_t)n * 1024 * 32;
    const float2* gp = (const float2*)g_grids + (size_t)n * 4 * 4096 + pix;

    float logit[4], vs[4];
#pragma unroll
    for (int p = 0; p < 4; p++) {
        float2 g = gp[(size_t)p * 4096];
        float x = (g.x + 1.f) * 16.f - 0.5f;
        float y = (g.y + 1.f) * 16.f - 0.5f;
        float x0f = floorf(x), y0f = floorf(y);
        float wx1 = x - x0f, wy1 = y - y0f;
        int x0 = (int)x0f, y0 = (int)y0f;
        float ks = 0.f, vv = 0.f;
#pragma unroll
        for (int dy = 0; dy < 2; dy++) {
#pragma unroll
            for (int dx = 0; dx < 2; dx++) {
                int xi = x0 + dx, yi = y0 + dy;
                float w = (dx ? wx1 : 1.f - wx1) * (dy ? wy1 : 1.f - wy1);
                if ((unsigned)xi < 32u && (unsigned)yi < 32u) {
                    int off = ((yi << 5) + xi) << 5;
                    ks = fmaf(w, kb[off + lane], ks);
                    vv = fmaf(w, vb[off + lane], vv);
                }
            }
        }
        float tsum = qv * ks;
#pragma unroll
        for (int o = 16; o > 0; o >>= 1)
            tsum += __shfl_xor_sync(0xffffffffu, tsum, o);
        logit[p] = tsum * 0.17677669529663687f;
        vs[p] = vv;
    }

    float mx = fmaxf(fmaxf(logit[0], logit[1]), fmaxf(logit[2], logit[3]));
    float e0 = expf(logit[0] - mx);
    float e1 = expf(logit[1] - mx);
    float e2 = expf(logit[2] - mx);
    float e3 = expf(logit[3] - mx);
    float inv = 1.f / (e0 + e1 + e2 + e3);
    float o = (e0 * vs[0] + e1 * vs[1] + e2 * vs[2] + e3 * vs[3]) * inv;

    uint16_t h, l;
    split_f16(o, h, l);
    size_t idx = ((size_t)b * 4096 + pix) * 256 + hh * 32 + lane;
    g_attnh[idx] = h;
    g_attnl[idx] = l;
}

// ----------------------------------------------------------------------------
extern "C" void kernel_launch(void* const* d_in, const int* in_sizes, int n_in,
                              void* d_out, int out_size)
{
    (void)in_sizes; (void)n_in; (void)out_size;
    const float* query = (const float*)d_in[0];
    const float* kv    = (const float*)d_in[1];
    const float* q_w   = (const float*)d_in[2];
    const float* k_w   = (const float*)d_in[3];
    const float* v_w   = (const float*)d_in[4];
    const float* off_w = (const float*)d_in[5];
    const float* off_b = (const float*)d_in[6];
    const float* out_w = (const float*)d_in[7];
    float* out = (float*)d_out;

    cudaFuncSetAttribute(mma_gemm<MODE_PROJ>,
                         cudaFuncAttributeMaxDynamicSharedMemorySize, PJ_SMEM);
    cudaFuncSetAttribute(mma_gemm<MODE_OUT>,
                         cudaFuncAttributeMaxDynamicSharedMemorySize, PJ_SMEM);
    cudaFuncSetAttribute(conv_tc_kernel,
                         cudaFuncAttributeMaxDynamicSharedMemorySize, CV_SMEM);

    uint16_t *xqh, *xql, *xkh, *xkl, *ath, *atl, *pwh;
    cudaGetSymbolAddress((void**)&xqh, g_xqh);
    cudaGetSymbolAddress((void**)&xql, g_xql);
    cudaGetSymbolAddress((void**)&xkh, g_xkh);
    cudaGetSymbolAddress((void**)&xkl, g_xkl);
    cudaGetSymbolAddress((void**)&ath, g_attnh);
    cudaGetSymbolAddress((void**)&atl, g_attnl);
    cudaGetSymbolAddress((void**)&pwh, g_pwh);

    // idx 0: merged preps
    prep_all_kernel<<<NBLK_IMG + NBLK_W + NBLK_PW, 256>>>(
        query, off_w, q_w, k_w, v_w, out_w);
    // idx 1-2: activation transpose+split
    tsplit_kernel<<<dim3(4096 / 32, 8, 8), 256>>>(query, xqh, xql, 4096);
    tsplit_kernel<<<dim3(1024 / 32, 8, 8), 256>>>(kv, xkh, xkl, 1024);
    // idx 3 (ncu capture slot): q projection
    mma_gemm<MODE_PROJ><<<dim3(64, 2, 8), 256, PJ_SMEM>>>(
        pwh + 0 * 65536, xqh, xql, nullptr, 4096, 0);
    // idx 4: offset conv split-K x2 (3 CTAs/SM)
    conv_tc_kernel<<<dim3(32, 8, 2), 256, CV_SMEM>>>();
    // idx 5: combine halves + tanh + base grid
    conv_combine_kernel<<<dim3(32, 8), 256>>>(off_b);
    // idx 6: stacked k+v projection (M=512)
    mma_gemm<MODE_PROJ><<<dim3(16, 4, 8), 256, PJ_SMEM>>>(
        pwh + 1 * 65536, xkh, xkl, nullptr, 1024, 3);
    // idx 7: attention
    attn_kernel<<<(64 * 4096) / 8, 256>>>();
    // idx 8: output projection
    mma_gemm<MODE_OUT><<<dim3(64, 2, 8), 256, PJ_SMEM>>>(
        pwh + 3 * 65536, ath, atl, out, 4096, 0);
}

// round 15
// speedup vs baseline: 1.7381x; 1.0061x over previous
#include <cuda_runtime.h>
#include <cuda_fp16.h>
#include <math.h>
#include <stdint.h>

// ----------------------------------------------------------------------------
// DeformableCrossAttention2D, split-fp16 mma.sync + ldmatrix (sm_100-safe).
// Value GEMMs: 2-product fp16 (4 CTAs/SM). Conv: 3-product fp16, split-K x2.
// ----------------------------------------------------------------------------

// ---------------- scratch (device globals; allocation-free rule) -------------
__device__ float g_q[64 * 4096 * 32];        // (n=b*H, pix, d)
__device__ float g_k[64 * 1024 * 32];
__device__ float g_v[64 * 1024 * 32];
__device__ float g_grids[64 * 4 * 4096 * 2]; // (n, p, pix, {x,y})
__device__ float g_cpart[2 * 8 * 4096 * 64]; // conv split-K partials [z][b][pix][oc]

__device__ __align__(16) uint32_t g_i2h[8 * 128 * 66 * 68]; // fp16-pair image hi
__device__ __align__(16) uint32_t g_i2l[8 * 128 * 66 * 68]; // lo
__device__ __align__(16) uint16_t g_wch[9 * 64 * 256];      // conv W hi
__device__ __align__(16) uint16_t g_wcl[9 * 64 * 256];      // conv W lo
__device__ __align__(16) uint16_t g_pwh[4 * 256 * 256];     // proj/out W hi
__device__ __align__(16) uint16_t g_xqh[8 * 4096 * 256];    // query^T split
__device__ __align__(16) uint16_t g_xql[8 * 4096 * 256];
__device__ __align__(16) uint16_t g_xkh[8 * 1024 * 256];    // kv^T split
__device__ __align__(16) uint16_t g_xkl[8 * 1024 * 256];
__device__ __align__(16) uint16_t g_attnh[8 * 4096 * 256];
__device__ __align__(16) uint16_t g_attnl[8 * 4096 * 256];

// ---------------- helpers ----------------------------------------------------
__device__ __forceinline__ void split_f16(float v, uint16_t& h, uint16_t& l) {
    __half hb = __float2half_rn(v);
    float r = v - __half2float(hb);
    h = __half_as_ushort(hb);
    l = __half_as_ushort(__float2half_rn(r));
}

__device__ __forceinline__ void mma_f16(float* c, const uint32_t* a, const uint32_t* b) {
    asm volatile(
        "mma.sync.aligned.m16n8k16.row.col.f32.f16.f16.f32 "
        "{%0,%1,%2,%3}, {%4,%5,%6,%7}, {%8,%9}, {%0,%1,%2,%3};"
        : "+f"(c[0]), "+f"(c[1]), "+f"(c[2]), "+f"(c[3])
        : "r"(a[0]), "r"(a[1]), "r"(a[2]), "r"(a[3]), "r"(b[0]), "r"(b[1]));
}

__device__ __forceinline__ void ldm_x4(uint32_t* r, uint32_t addr) {
    asm volatile("ldmatrix.sync.aligned.m8n8.x4.shared.b16 {%0,%1,%2,%3}, [%4];"
                 : "=r"(r[0]), "=r"(r[1]), "=r"(r[2]), "=r"(r[3]) : "r"(addr));
}

__device__ __forceinline__ uint32_t smem_u32(const void* p) {
    uint32_t a;
    asm("{ .reg .u64 t; cvta.to.shared.u64 t, %1; cvt.u32.u64 %0, t; }" : "=r"(a) : "l"(p));
    return a;
}
#define CP16(dst, src) \
    asm volatile("cp.async.cg.shared.global [%0], [%1], 16;" :: "r"(dst), "l"(src) : "memory")
#define CP_COMMIT() asm volatile("cp.async.commit_group;" ::: "memory")
#define CP_WAIT0()  asm volatile("cp.async.wait_group 0;" ::: "memory")

// ---------------- merged prep kernel -----------------------------------------
#define NBLK_IMG 17952
#define NBLK_W   576
#define NBLK_PW  1024

__global__ __launch_bounds__(256) void prep_all_kernel(
    const float* __restrict__ q, const float* __restrict__ cw,
    const float* __restrict__ w0, const float* __restrict__ w1,
    const float* __restrict__ w2, const float* __restrict__ w3)
{
    int blk = blockIdx.x;
    if (blk < NBLK_IMG) {
        int idx = blk * 256 + threadIdx.x;
        int b    = idx / (128 * 66 * 68);
        int rem  = idx - b * (128 * 66 * 68);
        int c2   = rem / (66 * 68);
        int rem2 = rem - c2 * (66 * 68);
        int y = rem2 / 68, x = rem2 - y * 68;
        uint16_t h0 = 0, l0 = 0, h1 = 0, l1 = 0;
        if (y >= 1 && y <= 64 && x >= 1 && x <= 64) {
            size_t base = ((size_t)(b * 256 + 2 * c2) * 64 + (y - 1)) * 64 + (x - 1);
            split_f16(q[base], h0, l0);
            split_f16(q[base + 4096], h1, l1);
        }
        g_i2h[idx] = (uint32_t)h0 | ((uint32_t)h1 << 16);
        g_i2l[idx] = (uint32_t)l0 | ((uint32_t)l1 << 16);
    } else if (blk < NBLK_IMG + NBLK_W) {
        int idx = (blk - NBLK_IMG) * 256 + threadIdx.x;
        int tap = idx >> 14;
        int rem = idx & 16383;
        int oc = rem >> 8, c = rem & 255;
        uint16_t h, l;
        split_f16(cw[(size_t)oc * 2304 + c * 9 + tap], h, l);
        g_wch[idx] = h;
        g_wcl[idx] = l;
    } else {
        int idx = (blk - NBLK_IMG - NBLK_W) * 256 + threadIdx.x;
        int slot = idx >> 16;
        int within = idx & 65535;
        const float* w = (slot == 0) ? w0 : (slot == 1) ? w1 : (slot == 2) ? w2 : w3;
        g_pwh[idx] = __half_as_ushort(__float2half_rn(w[within]));
    }
}

// ---------------- transpose+split activations --------------------------------
__global__ __launch_bounds__(256) void tsplit_kernel(
    const float* __restrict__ x, uint16_t* __restrict__ oh,
    uint16_t* __restrict__ ol, int Npix)
{
    __shared__ float tile[32][33];
    int p0 = blockIdx.x * 32, c0 = blockIdx.y * 32, b = blockIdx.z;
    int tx = threadIdx.x & 31, ty = threadIdx.x >> 5;
    const float* src = x + ((size_t)b * 256 + c0) * Npix + p0;
#pragma unroll
    for (int lq = 0; lq < 4; lq++) {
        int cc = ty + lq * 8;
        tile[cc][tx] = src[(size_t)cc * Npix + tx];
    }
    __syncthreads();
#pragma unroll
    for (int lq = 0; lq < 4; lq++) {
        int pp = ty + lq * 8;
        uint16_t h, l;
        split_f16(tile[tx][pp], h, l);
        size_t o = ((size_t)b * Npix + p0 + pp) * 256 + c0 + tx;
        oh[o] = h;
        ol[o] = l;
    }
}

// ---------------- PROJ / OUT 2-product fp16 GEMM (4 CTAs/SM) -----------------
enum { MODE_PROJ = 0, MODE_OUT = 1 };
#define PJ_SMEM 40960

template <int MODE>
__global__ __launch_bounds__(256, 4) void mma_gemm(
    const uint16_t* __restrict__ Ahg,
    const uint16_t* __restrict__ Bhg, const uint16_t* __restrict__ Blg,
    float* __restrict__ dst, int Npix, int which)
{
    extern __shared__ __align__(16) char smem[];
    const uint32_t smb = smem_u32(smem);

    const int t = threadIdx.x;
    const int lane = t & 31, wid = t >> 5;
    const int warp_m = wid & 3;
    const int warp_n = wid >> 2;
    const int bb = blockIdx.z;
    const int n0 = blockIdx.x * 64;
    const int m0 = blockIdx.y * 128;

    float c[2][4][4];
#pragma unroll
    for (int i = 0; i < 2; i++)
#pragma unroll
        for (int j = 0; j < 4; j++)
#pragma unroll
            for (int r = 0; r < 4; r++) c[i][j][r] = 0.f;

    const int am = t >> 1, ahalf = (t & 1) * 16;
    const int bn = t >> 2, bq = t & 3;

    auto stage = [&](int kb, int buf) {
        size_t aoff = (size_t)(m0 + am) * 256 + kb * 32 + ahalf;
        uint32_t adst = smb + buf * 10240 + (am * 40 + ahalf) * 2;
        CP16(adst, Ahg + aoff);
        CP16(adst + 16, Ahg + aoff + 8);
        size_t boff = ((size_t)bb * Npix + n0 + bn) * 256 + kb * 32 + bq * 8;
        uint32_t bdst = smb + 20480 + buf * 5120 + (bn * 40 + bq * 8) * 2;
        CP16(bdst, Bhg + boff);
        CP16(bdst + 10240, Blg + boff);
    };

    stage(0, 0);
    CP_COMMIT();

    const uint32_t aAddr = ((warp_m * 32 + (lane & 15)) * 40 + ((lane >> 4) * 8)) * 2;
    const uint32_t bAddr = ((warp_n * 32 + (lane & 7) + ((lane >> 4) << 3)) * 40
                            + (((lane >> 3) & 1) * 8)) * 2;

    for (int kb = 0; kb < 8; kb++) {
        const int buf = kb & 1;
        CP_WAIT0();
        __syncthreads();
        if (kb + 1 < 8) { stage(kb + 1, buf ^ 1); CP_COMMIT(); }

        const uint32_t baseAh = smb + buf * 10240 + aAddr;
        const uint32_t baseBh = smb + 20480 + buf * 5120 + bAddr;
        const uint32_t baseBl = smb + 30720 + buf * 5120 + bAddr;
#pragma unroll
        for (int ks = 0; ks < 2; ks++) {
            uint32_t ah[2][4], bh4[4][4], bl4[4][4];
            ldm_x4(ah[0], baseAh + ks * 32);
            ldm_x4(ah[1], baseAh + ks * 32 + 1280);
            ldm_x4(bh4[0], baseBh + ks * 32);
            ldm_x4(bh4[2], baseBh + ks * 32 + 1280);
            ldm_x4(bl4[0], baseBl + ks * 32);
            ldm_x4(bl4[2], baseBl + ks * 32 + 1280);
            uint32_t bfh[4][2], bfl[4][2];
#pragma unroll
            for (int j = 0; j < 4; j++) {
                bfh[j][0] = bh4[(j >> 1) * 2][(j & 1) * 2 + 0];
                bfh[j][1] = bh4[(j >> 1) * 2][(j & 1) * 2 + 1];
                bfl[j][0] = bl4[(j >> 1) * 2][(j & 1) * 2 + 0];
                bfl[j][1] = bl4[(j >> 1) * 2][(j & 1) * 2 + 1];
            }
#pragma unroll
            for (int i = 0; i < 2; i++)
#pragma unroll
                for (int j = 0; j < 4; j++)
                    mma_f16(c[i][j], ah[i], bfh[j]);
#pragma unroll
            for (int i = 0; i < 2; i++)
#pragma unroll
                for (int j = 0; j < 4; j++)
                    mma_f16(c[i][j], ah[i], bfl[j]);
        }
        __syncthreads();
    }

#pragma unroll
    for (int i = 0; i < 2; i++) {
#pragma unroll
        for (int j = 0; j < 4; j++) {
#pragma unroll
            for (int r = 0; r < 4; r++) {
                int mm = warp_m * 32 + i * 16 + (lane >> 2) + ((r & 2) ? 8 : 0);
                int nn = warp_n * 32 + j * 8 + (lane & 3) * 2 + (r & 1);
                float v = c[i][j][r];
                if (MODE == MODE_PROJ) {
                    int m = m0 + mm;
                    int n = n0 + nn;
                    float* dstp;
                    int mch;
                    if (which == 0) { dstp = g_q; mch = m; }
                    else { dstp = (m < 256) ? g_k : g_v; mch = m & 255; }
                    int hh = mch >> 5, d = mch & 31;
                    dstp[((size_t)(bb * 8 + hh) * Npix + n) * 32 + d] = v;
                } else {
                    int m = m0 + mm;
                    int n = n0 + nn;
                    dst[((size_t)bb * 256 + m) * 4096 + n] = v;
                }
            }
        }
    }
}

// ---------------- conv kernel (3-product, window reuse, split-K x2) ----------
#define CV_SMEM 56320

__global__ __launch_bounds__(256, 3) void conv_tc_kernel() {
    extern __shared__ __align__(16) char smem[];
    const uint32_t smb = smem_u32(smem);
    uint32_t* Ih = (uint32_t*)smem;                 // [16][280]
    uint32_t* Il = (uint32_t*)(smem + 17920);

    const int t = threadIdx.x;
    const int lane = t & 31, wid = t >> 5;
    const int warp_m = wid & 1;
    const int warp_n = wid >> 1;
    const int tile = blockIdx.x;
    const int bb = blockIdx.y;
    const int z = blockIdx.z;
    const int p0 = tile * 128;
    const int py0 = tile * 2;

    float c[2][4][4];
#pragma unroll
    for (int i = 0; i < 2; i++)
#pragma unroll
        for (int j = 0; j < 4; j++)
#pragma unroll
            for (int r = 0; r < 4; r++) c[i][j][r] = 0.f;

    auto stage_w = [&](int gi, int wb) {
        int cl = gi / 9, tap = gi - cl * 9;
        int cblk = z * 4 + cl;
        int oc = t >> 2, q = t & 3;
        size_t src = ((size_t)(tap * 64 + oc)) * 256 + cblk * 32 + q * 8;
        uint32_t dsth = smb + 35840 + (wb * 2560 + oc * 40 + q * 8) * 2;
        CP16(dsth, g_wch + src);
        CP16(dsth + 10240, g_wcl + src);
    };

    stage_w(0, 0);
    CP_COMMIT();

    const uint32_t aAddr = ((warp_m * 32 + (lane & 15)) * 40 + ((lane >> 4) * 8)) * 2;
    const int kq = lane & 3;

    for (int cl = 0; cl < 4; cl++) {
        const int cblk = z * 4 + cl;
        __syncthreads();
        for (int i = t; i < 1088; i += 256) {
            int rl = i / 17, xq = i - rl * 17;
            int c2 = rl >> 2, r = rl & 3;
            size_t src = (((size_t)(bb * 128 + cblk * 16 + c2)) * 66 + (py0 + r)) * 68 + xq * 4;
            int dstw = c2 * 280 + r * 68 + xq * 4;
            *(uint4*)(Ih + dstw) = *(const uint4*)(g_i2h + src);
            *(uint4*)(Il + dstw) = *(const uint4*)(g_i2l + src);
        }
        __syncthreads();

        for (int tap = 0; tap < 9; tap++) {
            const int gi = cl * 9 + tap;
            const int wb = gi & 1;
            CP_WAIT0();
            __syncthreads();
            if (gi + 1 < 36) { stage_w(gi + 1, wb ^ 1); CP_COMMIT(); }

            const int rowoff = tap / 3;
            const int xoff = tap - rowoff * 3;
            const uint32_t baseWh = smb + 35840 + wb * 5120 + aAddr;
            const uint32_t baseWl = smb + 46080 + wb * 5120 + aAddr;

#pragma unroll
            for (int ks = 0; ks < 2; ks++) {
                uint32_t ah[2][4], al[2][4], bh4[4][2], bl4[4][2];
                ldm_x4(ah[0], baseWh + ks * 32);
                ldm_x4(ah[1], baseWh + ks * 32 + 1280);
                ldm_x4(al[0], baseWl + ks * 32);
                ldm_x4(al[1], baseWl + ks * 32 + 1280);
                const int c2b = ks * 8 + kq;
#pragma unroll
                for (int j = 0; j < 4; j++) {
                    int n = warp_n * 32 + j * 8 + (lane >> 2);
                    int addr = c2b * 280 + ((n >> 6) + rowoff) * 68 + (n & 63) + xoff;
                    bh4[j][0] = Ih[addr];
                    bh4[j][1] = Ih[addr + 4 * 280];
                    bl4[j][0] = Il[addr];
                    bl4[j][1] = Il[addr + 4 * 280];
                }
#pragma unroll
                for (int i = 0; i < 2; i++)
#pragma unroll
                    for (int j = 0; j < 4; j++)
                        mma_f16(c[i][j], ah[i], bh4[j]);
#pragma unroll
                for (int i = 0; i < 2; i++)
#pragma unroll
                    for (int j = 0; j < 4; j++)
                        mma_f16(c[i][j], ah[i], bl4[j]);
#pragma unroll
                for (int i = 0; i < 2; i++)
#pragma unroll
                    for (int j = 0; j < 4; j++)
                        mma_f16(c[i][j], al[i], bh4[j]);
            }
        }
    }

#pragma unroll
    for (int i = 0; i < 2; i++) {
#pragma unroll
        for (int j = 0; j < 4; j++) {
#pragma unroll
            for (int r = 0; r < 4; r++) {
                int oc = warp_m * 32 + i * 16 + (lane >> 2) + ((r & 2) ? 8 : 0);
                int nn = warp_n * 32 + j * 8 + (lane & 3) * 2 + (r & 1);
                g_cpart[((size_t)(z * 8 + bb) * 4096 + p0 + nn) * 64 + oc] = c[i][j][r];
            }
        }
    }
}

// ---------------- conv combine: sum halves + bias + tanh + base grid ---------
__global__ __launch_bounds__(256) void conv_combine_kernel(const float* __restrict__ bias)
{
    __shared__ float s[128][65];
    const int t = threadIdx.x;
    const int tile = blockIdx.x, b = blockIdx.y;
    const int p0 = tile * 128;

    const float* src0 = g_cpart + ((size_t)b * 4096 + p0) * 64;
    const float* src1 = g_cpart + ((size_t)(8 + b) * 4096 + p0) * 64;
#pragma unroll
    for (int k = 0; k < 8; k++) {
        int vec = t + k * 256;
        int pixL = vec >> 4, oc4 = (vec & 15) * 4;
        float4 a = *(const float4*)(src0 + pixL * 64 + oc4);
        float4 bb4 = *(const float4*)(src1 + pixL * 64 + oc4);
        s[pixL][oc4 + 0] = a.x + bb4.x;
        s[pixL][oc4 + 1] = a.y + bb4.y;
        s[pixL][oc4 + 2] = a.z + bb4.z;
        s[pixL][oc4 + 3] = a.w + bb4.w;
    }
    __syncthreads();

    const int pixL = t & 127;
    const int mg = t >> 7;
    const int pix = p0 + pixL;
    const int px = pix & 63, py = pix >> 6;
    const float bx = px * (2.f / 63.f) - 1.f;
    const float by = py * (2.f / 63.f) - 1.f;
    float2* gout = (float2*)g_grids;
#pragma unroll
    for (int mi = 0; mi < 16; mi++) {
        int m = mg * 16 + mi;
        int oc = 2 * m;
        float w0 = tanhf(s[pixL][oc] + __ldg(&bias[oc])) * 0.25f + bx;
        float w1 = tanhf(s[pixL][oc + 1] + __ldg(&bias[oc + 1])) * 0.25f + by;
        int hh = m >> 2, p = m & 3;
        gout[((size_t)((b * 8 + hh) * 4 + p) * 4096) + pix] = make_float2(w0, w1);
    }
}

// ---------------- attention (global loads, high occupancy) -------------------
__global__ __launch_bounds__(256) void attn_kernel()
{
    int gw   = blockIdx.x * 8 + (threadIdx.x >> 5);
    int lane = threadIdx.x & 31;
    int n    = gw >> 12;
    int pix  = gw & 4095;
    int b    = n >> 3;
    int hh   = n & 7;

    float qv = g_q[((size_t)n * 4096 + pix) * 32 + lane];
    const float* kb = g_k + (size_t)n * 1024 * 32;
    const float* vb = g_v + (size_t)n * 1024 * 32;
    const float2* gp = (const float2*)g_grids + (size_t)n * 4 * 4096 + pix;

    float logit[4], vs[4];
#pragma unroll
    for (int p = 0; p < 4; p++) {
        float2 g = gp[(size_t)p * 4096];
        float x = (g.x + 1.f) * 16.f - 0.5f;
        float y = (g.y + 1.f) * 16.f - 0.5f;
        float x0f = floorf(x), y0f = floorf(y);
        float wx1 = x - x0f, wy1 = y - y0f;
        int x0 = (int)x0f, y0 = (int)y0f;
        float ks = 0.f, vv = 0.f;
#pragma unroll
        for (int dy = 0; dy < 2; dy++) {
#pragma unroll
            for (int dx = 0; dx < 2; dx++) {
                int xi = x0 + dx, yi = y0 + dy;
                float w = (dx ? wx1 : 1.f - wx1) * (dy ? wy1 : 1.f - wy1);
                if ((unsigned)xi < 32u && (unsigned)yi < 32u) {
                    int off = ((yi << 5) + xi) << 5;
                    ks = fmaf(w, kb[off + lane], ks);
                    vv = fmaf(w, vb[off + lane], vv);
                }
            }
        }
        float tsum = qv * ks;
#pragma unroll
        for (int o = 16; o > 0; o >>= 1)
            tsum += __shfl_xor_sync(0xffffffffu, tsum, o);
        logit[p] = tsum * 0.17677669529663687f;
        vs[p] = vv;
    }

    float mx = fmaxf(fmaxf(logit[0], logit[1]), fmaxf(logit[2], logit[3]));
    float e0 = expf(logit[0] - mx);
    float e1 = expf(logit[1] - mx);
    float e2 = expf(logit[2] - mx);
    float e3 = expf(logit[3] - mx);
    float inv = 1.f / (e0 + e1 + e2 + e3);
    float o = (e0 * vs[0] + e1 * vs[1] + e2 * vs[2] + e3 * vs[3]) * inv;

    uint16_t h, l;
    split_f16(o, h, l);
    size_t idx = ((size_t)b * 4096 + pix) * 256 + hh * 32 + lane;
    g_attnh[idx] = h;
    g_attnl[idx] = l;
}

// ----------------------------------------------------------------------------
extern "C" void kernel_launch(void* const* d_in, const int* in_sizes, int n_in,
                              void* d_out, int out_size)
{
    (void)in_sizes; (void)n_in; (void)out_size;
    const float* query = (const float*)d_in[0];
    const float* kv    = (const float*)d_in[1];
    const float* q_w   = (const float*)d_in[2];
    const float* k_w   = (const float*)d_in[3];
    const float* v_w   = (const float*)d_in[4];
    const float* off_w = (const float*)d_in[5];
    const float* off_b = (const float*)d_in[6];
    const float* out_w = (const float*)d_in[7];
    float* out = (float*)d_out;

    cudaFuncSetAttribute(mma_gemm<MODE_PROJ>,
                         cudaFuncAttributeMaxDynamicSharedMemorySize, PJ_SMEM);
    cudaFuncSetAttribute(mma_gemm<MODE_OUT>,
                         cudaFuncAttributeMaxDynamicSharedMemorySize, PJ_SMEM);
    cudaFuncSetAttribute(conv_tc_kernel,
                         cudaFuncAttributeMaxDynamicSharedMemorySize, CV_SMEM);

    uint16_t *xqh, *xql, *xkh, *xkl, *ath, *atl, *pwh;
    cudaGetSymbolAddress((void**)&xqh, g_xqh);
    cudaGetSymbolAddress((void**)&xql, g_xql);
    cudaGetSymbolAddress((void**)&xkh, g_xkh);
    cudaGetSymbolAddress((void**)&xkl, g_xkl);
    cudaGetSymbolAddress((void**)&ath, g_attnh);
    cudaGetSymbolAddress((void**)&atl, g_attnl);
    cudaGetSymbolAddress((void**)&pwh, g_pwh);

    // idx 0: merged preps
    prep_all_kernel<<<NBLK_IMG + NBLK_W + NBLK_PW, 256>>>(
        query, off_w, q_w, k_w, v_w, out_w);
    // idx 1-2: activation transpose+split
    tsplit_kernel<<<dim3(4096 / 32, 8, 8), 256>>>(query, xqh, xql, 4096);
    tsplit_kernel<<<dim3(1024 / 32, 8, 8), 256>>>(kv, xkh, xkl, 1024);
    // idx 3 (ncu capture slot): q projection
    mma_gemm<MODE_PROJ><<<dim3(64, 2, 8), 256, PJ_SMEM>>>(
        pwh + 0 * 65536, xqh, xql, nullptr, 4096, 0);
    // idx 4: offset conv split-K x2
    conv_tc_kernel<<<dim3(32, 8, 2), 256, CV_SMEM>>>();
    // idx 5: combine halves + tanh + base grid
    conv_combine_kernel<<<dim3(32, 8), 256>>>(off_b);
    // idx 6: stacked k+v projection (M=512)
    mma_gemm<MODE_PROJ><<<dim3(16, 4, 8), 256, PJ_SMEM>>>(
        pwh + 1 * 65536, xkh, xkl, nullptr, 1024, 3);
    // idx 7: attention
    attn_kernel<<<(64 * 4096) / 8, 256>>>();
    // idx 8: output projection
    mma_gemm<MODE_OUT><<<dim3(64, 2, 8), 256, PJ_SMEM>>>(
        pwh + 3 * 65536, ath, atl, out, 4096, 0);
}